// round 2
// baseline (speedup 1.0000x reference)
#include <cuda_runtime.h>
#include <cuda_bf16.h>
#include <cstdint>

#define N_TRAIN 8192
#define M_PTS   8192
#define D_DIM   256

#define BM 128          // x_train rows per tile iteration
#define BN 64           // output columns per CTA
#define S_SPLIT 2       // N-dimension split across CTAs
#define LDS_A 264       // padded smem row stride (elements) -> conflict-free LDS
#define NTHREADS 256

// c = (1/sigma)^2 = 1/1024 ; KC = c * log2(e), so exp(-c*sq) = exp2(KC*(2*dot - n2 - m2))
static __device__ __constant__ float KCONST = 1.4426950408889634f / 1024.0f;
#define KC_HOST (1.4426950408889634f / 1024.0f)

// ---- device scratch (static allocations are allowed) ----
__device__ __nv_bfloat16 g_A[(size_t)N_TRAIN * D_DIM];  // x_train bf16
__device__ __nv_bfloat16 g_Bm[(size_t)M_PTS * D_DIM];   // x bf16
__device__ float g_w[N_TRAIN];                          // alpha * y_train
__device__ float g_kn2[N_TRAIN];                        // KC * ||x_train_n||^2 (bf16-rounded vals)
__device__ float g_km2[M_PTS];                          // KC * ||x_m||^2
__device__ float g_part[S_SPLIT * M_PTS];               // split partial sums

// ---------------------------------------------------------------------------
// Kernel 1: convert to bf16, compute scaled squared norms, compute w
// one block (128 thr) per row; blocks [0,N) -> x_train, [N, N+M) -> x
// ---------------------------------------------------------------------------
__global__ void prep_kernel(const float* __restrict__ xt, const float* __restrict__ yt,
                            const float* __restrict__ al, const float* __restrict__ x) {
    __shared__ float red[4];
    int b = blockIdx.x;
    int t = threadIdx.x;
    bool isA = (b < N_TRAIN);
    const float* src;
    __nv_bfloat16* dst;
    if (isA) { src = xt + (size_t)b * D_DIM; dst = g_A + (size_t)b * D_DIM; }
    else     { src = x + (size_t)(b - N_TRAIN) * D_DIM; dst = g_Bm + (size_t)(b - N_TRAIN) * D_DIM; }

    float ss = 0.f;
#pragma unroll
    for (int j = 0; j < D_DIM / 128; j++) {
        int i = t + j * 128;
        float v = src[i];
        __nv_bfloat16 h = __float2bfloat16(v);
        float hv = __bfloat162float(h);
        ss += hv * hv;
        dst[i] = h;
    }
#pragma unroll
    for (int o = 16; o > 0; o >>= 1) ss += __shfl_down_sync(0xffffffffu, ss, o);
    if ((t & 31) == 0) red[t >> 5] = ss;
    __syncthreads();
    if (t == 0) {
        float tot = (red[0] + red[1] + red[2] + red[3]) * KCONST;
        if (isA) { g_kn2[b] = tot; g_w[b] = al[b] * yt[b]; }
        else     { g_km2[b - N_TRAIN] = tot; }
    }
}

// ---------------------------------------------------------------------------
// Kernel 2: fused GEMM (bf16 mma.sync) + exp epilogue + column reduction.
// CTA: BM x BN tile, 8 warps in 4(row) x 2(col) layout, warp tile 32x32.
// x tile (BN x 256) resident in SMEM for the whole CTA; x_train streamed.
// ---------------------------------------------------------------------------
extern "C" __global__ void __launch_bounds__(NTHREADS, 2)
svm_main_kernel() {
    extern __shared__ char smem_raw[];
    __nv_bfloat16* sA = (__nv_bfloat16*)smem_raw;          // BM x LDS_A
    __nv_bfloat16* sB = sA + (size_t)BM * LDS_A;           // BN x LDS_A
    float* sW   = (float*)(sB + (size_t)BN * LDS_A);       // BM
    float* sKN2 = sW + BM;                                 // BM
    float* sKM2 = sKN2 + BM;                               // BN
    float* sRed = sKM2 + BN;                               // 4 * BN

    const int tid  = threadIdx.x;
    const int lane = tid & 31;
    const int wid  = tid >> 5;
    const int wr   = wid >> 1;   // warp row 0..3
    const int wc   = wid & 1;    // warp col 0..1
    const int m0   = blockIdx.x * BN;
    const int n0   = blockIdx.y * (N_TRAIN / S_SPLIT);

    // ---- load resident B (x) tile: BN x 256 bf16, 16B vectors ----
    {
        const uint4* src = (const uint4*)(g_Bm + (size_t)m0 * D_DIM);
        for (int i = tid; i < BN * (D_DIM / 8); i += NTHREADS) {
            int row = i >> 5;       // D_DIM/8 = 32 uint4 per row
            int c8  = i & 31;
            uint4 v = src[i];
            *(uint4*)&sB[row * LDS_A + c8 * 8] = v;
        }
        if (tid < BN) sKM2[tid] = g_km2[m0 + tid];
    }
    __syncthreads();

    // per-thread column scalars (fixed for whole kernel)
    float km2v[8];
#pragma unroll
    for (int cf = 0; cf < 4; cf++)
#pragma unroll
        for (int h = 0; h < 2; h++)
            km2v[cf * 2 + h] = sKM2[wc * 32 + cf * 8 + (lane & 3) * 2 + h];

    float colacc[8];
#pragma unroll
    for (int j = 0; j < 8; j++) colacc[j] = 0.f;

    const float k2x = 2.f * KCONST;
    const int ITERS = (N_TRAIN / S_SPLIT) / BM;   // 32

    for (int it = 0; it < ITERS; it++) {
        const int r0 = n0 + it * BM;
        __syncthreads();  // previous iteration fully consumed sA/sW/sKN2

        // ---- stream A (x_train) tile: BM x 256 bf16 ----
        {
            const uint4* srcA = (const uint4*)(g_A + (size_t)r0 * D_DIM);
#pragma unroll
            for (int j = 0; j < (BM * (D_DIM / 8)) / NTHREADS; j++) {  // 16
                int i = tid + j * NTHREADS;
                int row = i >> 5;
                int c8  = i & 31;
                uint4 v = srcA[i];
                *(uint4*)&sA[row * LDS_A + c8 * 8] = v;
            }
            if (tid < BM) sW[tid] = g_w[r0 + tid];
            else          sKN2[tid - BM] = g_kn2[r0 + tid - BM];
        }
        __syncthreads();

        // ---- GEMM: warp tile 32x32, mma.m16n8k16 bf16 ----
        float acc[32];
#pragma unroll
        for (int i = 0; i < 32; i++) acc[i] = 0.f;

        const __nv_bfloat16* aBase = sA + (wr * 32 + (lane >> 2)) * LDS_A + (lane & 3) * 2;
        const __nv_bfloat16* bBase = sB + (wc * 32 + (lane >> 2)) * LDS_A + (lane & 3) * 2;

#pragma unroll 4
        for (int ko = 0; ko < D_DIM; ko += 16) {
            uint32_t a[2][4], bf[4][2];
#pragma unroll
            for (int rf = 0; rf < 2; rf++) {
                const __nv_bfloat16* p = aBase + rf * 16 * LDS_A + ko;
                a[rf][0] = *(const uint32_t*)(p);
                a[rf][1] = *(const uint32_t*)(p + 8 * LDS_A);
                a[rf][2] = *(const uint32_t*)(p + 8);
                a[rf][3] = *(const uint32_t*)(p + 8 * LDS_A + 8);
            }
#pragma unroll
            for (int cf = 0; cf < 4; cf++) {
                const __nv_bfloat16* p = bBase + cf * 8 * LDS_A + ko;
                bf[cf][0] = *(const uint32_t*)(p);
                bf[cf][1] = *(const uint32_t*)(p + 8);
            }
#pragma unroll
            for (int rf = 0; rf < 2; rf++)
#pragma unroll
                for (int cf = 0; cf < 4; cf++) {
                    float* c = &acc[rf * 16 + cf * 4];
                    asm volatile(
                        "mma.sync.aligned.m16n8k16.row.col.f32.bf16.bf16.f32 "
                        "{%0,%1,%2,%3}, {%4,%5,%6,%7}, {%8,%9}, {%0,%1,%2,%3};\n"
                        : "+f"(c[0]), "+f"(c[1]), "+f"(c[2]), "+f"(c[3])
                        : "r"(a[rf][0]), "r"(a[rf][1]), "r"(a[rf][2]), "r"(a[rf][3]),
                          "r"(bf[cf][0]), "r"(bf[cf][1]));
                }
        }

        // ---- epilogue: exp + weighted accumulate into register column sums ----
#pragma unroll
        for (int rf = 0; rf < 2; rf++)
#pragma unroll
            for (int rh = 0; rh < 2; rh++) {
                int rowl = wr * 32 + rf * 16 + rh * 8 + (lane >> 2);
                float wrow = sW[rowl];
                float tr   = sKN2[rowl];
#pragma unroll
                for (int cf = 0; cf < 4; cf++)
#pragma unroll
                    for (int h = 0; h < 2; h++) {
                        float d = acc[rf * 16 + cf * 4 + rh * 2 + h];
                        float arg = fmaf(d, k2x, -(tr + km2v[cf * 2 + h]));
                        arg = fminf(arg, 0.f);   // sq = max(sq, 0)
                        float e;
                        asm("ex2.approx.ftz.f32 %0, %1;" : "=f"(e) : "f"(arg));
                        colacc[cf * 2 + h] = fmaf(e, wrow, colacc[cf * 2 + h]);
                    }
            }
    }

    // ---- deterministic cross-thread / cross-warp column reduction ----
#pragma unroll
    for (int j = 0; j < 8; j++) {
        float v = colacc[j];
        v += __shfl_xor_sync(0xffffffffu, v, 4);
        v += __shfl_xor_sync(0xffffffffu, v, 8);
        v += __shfl_xor_sync(0xffffffffu, v, 16);
        colacc[j] = v;
    }
    if (lane < 4) {
#pragma unroll
        for (int j = 0; j < 8; j++) {
            int col = wc * 32 + (j >> 1) * 8 + lane * 2 + (j & 1);
            sRed[wr * BN + col] = colacc[j];
        }
    }
    __syncthreads();
    if (tid < BN) {
        float s = sRed[tid] + sRed[BN + tid] + sRed[2 * BN + tid] + sRed[3 * BN + tid];
        g_part[blockIdx.y * M_PTS + m0 + tid] = s;
    }
}

// ---------------------------------------------------------------------------
// Kernel 3: combine the S_SPLIT partials (deterministic)
// ---------------------------------------------------------------------------
__global__ void reduce_kernel(float* __restrict__ out) {
    int m = blockIdx.x * blockDim.x + threadIdx.x;
    if (m < M_PTS) out[m] = g_part[m] + g_part[M_PTS + m];
}

// ---------------------------------------------------------------------------
extern "C" void kernel_launch(void* const* d_in, const int* in_sizes, int n_in,
                              void* d_out, int out_size) {
    const float* xt = (const float*)d_in[0];   // x_train [8192,256]
    const float* yt = (const float*)d_in[1];   // y_train [8192]
    const float* al = (const float*)d_in[2];   // alpha   [8192]
    const float* x  = (const float*)d_in[3];   // x       [8192,256]

    size_t smem = (size_t)(BM + BN) * LDS_A * sizeof(__nv_bfloat16)
                + (size_t)(BM + BM + BN + 4 * BN) * sizeof(float);

    cudaFuncSetAttribute(svm_main_kernel,
                         cudaFuncAttributeMaxDynamicSharedMemorySize, (int)smem);

    prep_kernel<<<N_TRAIN + M_PTS, 128>>>(xt, yt, al, x);
    svm_main_kernel<<<dim3(M_PTS / BN, S_SPLIT), NTHREADS, smem>>>();
    reduce_kernel<<<(M_PTS + 255) / 256, 256>>>((float*)d_out);
}

// round 4
// speedup vs baseline: 1.2697x; 1.2697x over previous
#include <cuda_runtime.h>
#include <cuda_bf16.h>
#include <cstdint>

#define N_TRAIN 8192
#define M_PTS   8192
#define D_DIM   256
#define S_SPLIT 2
#define ROWS_PER_SPLIT (N_TRAIN / S_SPLIT)   // 4096
#define BM 128          // x_train rows per iteration (streamed)
#define BN 128          // x points per CTA (resident, output cols)
#define ITERS (ROWS_PER_SPLIT / BM)          // 32
#define NTHREADS 256

#define KC (1.4426950408889634f / 1024.0f)   // (1/sigma)^2 * log2(e)

// SMEM offsets (bytes). Tiles are 128 rows x 512B (256 bf16), XOR-swizzled:
// physical 16B chunk = logical chunk ^ (row & 7).
#define OFF_B   0           // x tile (resident)        64KB
#define OFF_A0  65536       // x_train tile stage 0     64KB
#define OFF_A1  131072      // x_train tile stage 1     64KB
#define OFF_W0  196608      // {w, kn2} stage 0          1KB
#define OFF_W1  197632      // {w, kn2} stage 1          1KB
#define OFF_RED 198656      // cross-warp reduce         1KB
#define SMEM_REQ 199680

__device__ __nv_bfloat16 g_A[(size_t)N_TRAIN * D_DIM];   // x_train bf16
__device__ __nv_bfloat16 g_Bm[(size_t)M_PTS * D_DIM];    // x bf16
__device__ float2 g_wn2[N_TRAIN];                        // {alpha*y, KC*||xt||^2}
__device__ float  g_km2[M_PTS];                          // KC*||x||^2
__device__ float  g_part[S_SPLIT * M_PTS];

// ---------------------------------------------------------------- helpers
__device__ __forceinline__ uint32_t smem_u32(const void* p) {
    uint32_t a;
    asm("{ .reg .u64 t; cvta.to.shared.u64 t, %1; cvt.u32.u64 %0, t; }"
        : "=r"(a) : "l"(p));
    return a;
}

__device__ __forceinline__ void mma16816(float* c, const uint32_t* a,
                                         uint32_t b0, uint32_t b1) {
    asm volatile(
        "mma.sync.aligned.m16n8k16.row.col.f32.bf16.bf16.f32 "
        "{%0,%1,%2,%3}, {%4,%5,%6,%7}, {%8,%9}, {%0,%1,%2,%3};\n"
        : "+f"(c[0]), "+f"(c[1]), "+f"(c[2]), "+f"(c[3])
        : "r"(a[0]), "r"(a[1]), "r"(a[2]), "r"(a[3]), "r"(b0), "r"(b1));
}

#define LDSM_X4(r0, r1, r2, r3, addr)                                        \
    asm volatile("ldmatrix.sync.aligned.m8n8.x4.shared.b16 {%0,%1,%2,%3}, [%4];" \
                 : "=r"(r0), "=r"(r1), "=r"(r2), "=r"(r3) : "r"(addr))

// 128x256 bf16 tile (64KB): global (row-major) -> swizzled SMEM via cp.async
__device__ __forceinline__ void cp_tile(uint32_t dst, const __nv_bfloat16* src, int tid) {
    const char* g = (const char*)src;
#pragma unroll
    for (int j = 0; j < 16; j++) {
        int idx = tid + j * NTHREADS;                 // 0..4095 16B chunks
        int row = idx >> 5;
        int ch  = idx & 31;
        uint32_t so = dst + (uint32_t)row * 512 + (uint32_t)((ch ^ (row & 7)) << 4);
        asm volatile("cp.async.cg.shared.global [%0], [%1], 16;"
                     :: "r"(so), "l"(g + (size_t)idx * 16) : "memory");
    }
}

// ---------------------------------------------------------------- prep
__global__ void __launch_bounds__(256) prep_kernel(const float* __restrict__ xt,
                                                   const float* __restrict__ yt,
                                                   const float* __restrict__ al,
                                                   const float* __restrict__ x) {
    int w    = blockIdx.x * 8 + (threadIdx.x >> 5);
    int lane = threadIdx.x & 31;
    bool isA = (w < N_TRAIN);
    const float* src = isA ? xt + (size_t)w * D_DIM
                           : x + (size_t)(w - N_TRAIN) * D_DIM;
    __nv_bfloat16* dst = isA ? g_A + (size_t)w * D_DIM
                             : g_Bm + (size_t)(w - N_TRAIN) * D_DIM;
    float ss = 0.f;
#pragma unroll
    for (int j = 0; j < 2; j++) {
        float4 v = ((const float4*)src)[lane + 32 * j];
        __nv_bfloat16 h0 = __float2bfloat16(v.x), h1 = __float2bfloat16(v.y);
        __nv_bfloat16 h2 = __float2bfloat16(v.z), h3 = __float2bfloat16(v.w);
        float a0 = __bfloat162float(h0), a1 = __bfloat162float(h1);
        float a2 = __bfloat162float(h2), a3 = __bfloat162float(h3);
        ss += a0 * a0 + a1 * a1 + a2 * a2 + a3 * a3;
        uint2 u;
        u.x = (uint32_t)__bfloat16_as_ushort(h0) | ((uint32_t)__bfloat16_as_ushort(h1) << 16);
        u.y = (uint32_t)__bfloat16_as_ushort(h2) | ((uint32_t)__bfloat16_as_ushort(h3) << 16);
        ((uint2*)dst)[lane + 32 * j] = u;
    }
#pragma unroll
    for (int o = 16; o > 0; o >>= 1) ss += __shfl_xor_sync(0xffffffffu, ss, o);
    if (lane == 0) {
        if (isA) g_wn2[w] = make_float2(al[w] * yt[w], ss * KC);
        else     g_km2[w - N_TRAIN] = ss * KC;
    }
}

// ---------------------------------------------------------------- main
extern "C" __global__ void __launch_bounds__(NTHREADS, 1) svm_main_kernel() {
    extern __shared__ char smem_raw[];
    const uint32_t s_base = smem_u32(smem_raw);
    const uint32_t sB_u   = s_base + OFF_B;
    const uint32_t sA_u[2] = { s_base + OFF_A0, s_base + OFF_A1 };
    const uint32_t sW_u[2] = { s_base + OFF_W0, s_base + OFF_W1 };
    float* sRed = (float*)(smem_raw + OFF_RED);

    const int tid  = threadIdx.x;
    const int lane = tid & 31;
    const int wid  = tid >> 5;
    const int wr   = wid >> 2;     // 0..1 : 64-row band
    const int wc   = wid & 3;      // 0..3 : 32-col band
    const int m0   = blockIdx.x * BN;               // x-point base (cols)
    const int n0   = blockIdx.y * ROWS_PER_SPLIT;   // x_train base (rows)

    // per-thread column constants
    float km2v[8];
#pragma unroll
    for (int nf = 0; nf < 4; nf++)
#pragma unroll
        for (int h = 0; h < 2; h++)
            km2v[nf * 2 + h] = __ldg(&g_km2[m0 + wc * 32 + nf * 8 + (lane & 3) * 2 + h]);

    // prologue loads: resident B (x tile), A stage 0, wn2 stage 0
    cp_tile(sB_u, g_Bm + (size_t)m0 * D_DIM, tid);
    cp_tile(sA_u[0], g_A + (size_t)n0 * D_DIM, tid);
    if (tid < 64)
        asm volatile("cp.async.cg.shared.global [%0], [%1], 16;"
                     :: "r"(sW_u[0] + tid * 16),
                        "l"((const char*)(g_wn2 + n0) + tid * 16) : "memory");
    asm volatile("cp.async.commit_group;");
    asm volatile("cp.async.wait_group 0;");
    __syncthreads();

    // ldmatrix per-lane bases (tile-row * 512B); xr/csel give the swizzled chunk
    const uint32_t aro  = (uint32_t)(wr * 64 + (lane & 15)) * 512;
    const uint32_t bro  = (uint32_t)(wc * 32 + (lane & 15)) * 512;
    const uint32_t csel = (uint32_t)(lane >> 4) & 1u;
    const uint32_t xr7  = (uint32_t)(lane & 7);

    float colacc[8];
#pragma unroll
    for (int j = 0; j < 8; j++) colacc[j] = 0.f;
    const float k2x = 2.f * KC;

    for (int i = 0; i < ITERS; i++) {
        const int s = i & 1;

        // prefetch next stage (fully overlapped with the MMA body below)
        if (i + 1 < ITERS) {
            cp_tile(sA_u[s ^ 1], g_A + (size_t)(n0 + (i + 1) * BM) * D_DIM, tid);
            if (tid < 64)
                asm volatile("cp.async.cg.shared.global [%0], [%1], 16;"
                             :: "r"(sW_u[s ^ 1] + tid * 16),
                                "l"((const char*)(g_wn2 + n0 + (i + 1) * BM) + tid * 16)
                             : "memory");
        }
        asm volatile("cp.async.commit_group;");

        // ---- GEMM: 128x128x256 tile via ldmatrix + mma.sync ----
        float acc[4][4][4];
#pragma unroll
        for (int mf = 0; mf < 4; mf++)
#pragma unroll
            for (int nf = 0; nf < 4; nf++)
#pragma unroll
                for (int q = 0; q < 4; q++) acc[mf][nf][q] = 0.f;

        const uint32_t aB = sA_u[s] + aro;
        const uint32_t bB = sB_u + bro;

#pragma unroll
        for (int ks = 0; ks < 16; ks++) {
            const uint32_t coff = (((2u * ks + csel) ^ xr7) << 4);
            uint32_t a[4][4], bq[2][4];
#pragma unroll
            for (int mf = 0; mf < 4; mf++)
                LDSM_X4(a[mf][0], a[mf][1], a[mf][2], a[mf][3], aB + mf * 8192 + coff);
#pragma unroll
            for (int p = 0; p < 2; p++)
                LDSM_X4(bq[p][0], bq[p][1], bq[p][2], bq[p][3], bB + p * 8192 + coff);
#pragma unroll
            for (int mf = 0; mf < 4; mf++)
#pragma unroll
                for (int ng = 0; ng < 4; ng++)
                    mma16816(acc[mf][ng], a[mf],
                             bq[ng >> 1][ng & 1], bq[ng >> 1][(ng & 1) + 2]);
        }

        // ---- epilogue: exp + weighted accumulate (reduce over rows) ----
        const uint32_t wbase = sW_u[s];
#pragma unroll
        for (int mf = 0; mf < 4; mf++)
#pragma unroll
            for (int rh = 0; rh < 2; rh++) {
                const uint32_t rowl = (uint32_t)(wr * 64 + mf * 16 + rh * 8 + (lane >> 2));
                float wj, n2j;
                asm("ld.shared.v2.f32 {%0,%1}, [%2];"
                    : "=f"(wj), "=f"(n2j) : "r"(wbase + rowl * 8));
#pragma unroll
                for (int nf = 0; nf < 4; nf++)
#pragma unroll
                    for (int h = 0; h < 2; h++) {
                        float d = acc[mf][nf][rh * 2 + h];
                        float arg = fmaf(d, k2x, -n2j) - km2v[nf * 2 + h];
                        arg = fminf(arg, 0.f);
                        float e;
                        asm("ex2.approx.ftz.f32 %0, %1;" : "=f"(e) : "f"(arg));
                        colacc[nf * 2 + h] = fmaf(e, wj, colacc[nf * 2 + h]);
                    }
            }

        asm volatile("cp.async.wait_group 0;");
        __syncthreads();
    }

    // ---- deterministic column reduction ----
#pragma unroll
    for (int j = 0; j < 8; j++) {
        float v = colacc[j];
        v += __shfl_xor_sync(0xffffffffu, v, 4);
        v += __shfl_xor_sync(0xffffffffu, v, 8);
        v += __shfl_xor_sync(0xffffffffu, v, 16);
        colacc[j] = v;
    }
    if (lane < 4) {
#pragma unroll
        for (int j = 0; j < 8; j++) {
            int col = wc * 32 + (j >> 1) * 8 + lane * 2 + (j & 1);
            sRed[wr * BN + col] = colacc[j];
        }
    }
    __syncthreads();
    if (tid < BN) {
        float sv = sRed[tid] + sRed[BN + tid];
        g_part[blockIdx.y * M_PTS + m0 + tid] = sv;
    }
}

// ---------------------------------------------------------------- reduce
__global__ void reduce_kernel(float* __restrict__ out) {
    int m = blockIdx.x * blockDim.x + threadIdx.x;
    if (m < M_PTS) out[m] = g_part[m] + g_part[M_PTS + m];
}

// ---------------------------------------------------------------- launch
extern "C" void kernel_launch(void* const* d_in, const int* in_sizes, int n_in,
                              void* d_out, int out_size) {
    const float* xt = (const float*)d_in[0];
    const float* yt = (const float*)d_in[1];
    const float* al = (const float*)d_in[2];
    const float* x  = (const float*)d_in[3];

    cudaFuncSetAttribute(svm_main_kernel,
                         cudaFuncAttributeMaxDynamicSharedMemorySize, SMEM_REQ);

    prep_kernel<<<(N_TRAIN + M_PTS) / 8, 256>>>(xt, yt, al, x);
    svm_main_kernel<<<dim3(M_PTS / BN, S_SPLIT), NTHREADS, SMEM_REQ>>>();
    reduce_kernel<<<(M_PTS + 255) / 256, 256>>>((float*)d_out);
}